// round 13
// baseline (speedup 1.0000x reference)
#include <cuda_runtime.h>
#include <cuda_fp16.h>
#include <cstdint>

#define D    128
#define NGc  10000
#define NUc  100000
#define NIc  20000
#define EGIc 400000
#define EGUc 400000

// ---------------- scratch (device globals; no allocation allowed) -------------
struct ZeroRegion {
    int cnt_i[NGc];
    int cnt_u[NGc];
    int pos_i[NGc];
    int pos_u[NGc];
};
__device__ ZeroRegion g_zr;

__device__ int    g_off_i[NGc];
__device__ int    g_off_u[NGc];
__device__ int    g_nbr_i[EGIc];
__device__ int    g_nbr_u[EGUc];
__device__ __half g_embih[NIc * D];
__device__ __half g_embuh[NUc * D];
__device__ __half g_Wt[2 * D * D];      // Wr1[0]^T, Wr1[2]^T fp16
__device__ __half g_W1c[D * 256];       // [Wl1[1];Wl1[3]]^T
__device__ __half g_W2c[D * 384];       // [Wl2[1];Wl2[3];Wr2[1]+Wr2[3]]^T
__device__ __half g_X1[NGc * 256];      // [aggI, aggU] fp16
__device__ __half g_X2[NGc * 384];      // [agg2I, agg2U, g1] fp16
__device__ __half g_i1h[NIc * D];
__device__ __half g_u1h[NUc * D];
__device__ __half g_Af[NGc * D];        // g2 fp16
__device__ __half g_Bf[NIc * D];        // WpT fp16: [n][k]

// ---------------- helpers -------------------------------------------------------
__device__ __forceinline__ float4 h4_to_f4(uint2 r)
{
    __half2 a = *(__half2*)&r.x;
    __half2 b = *(__half2*)&r.y;
    float2 fa = __half22float2(a), fb = __half22float2(b);
    return make_float4(fa.x, fa.y, fb.x, fb.y);
}
__device__ __forceinline__ uint2 f4_to_h4(float4 v)
{
    __half2 a = __floats2half2_rn(v.x, v.y);
    __half2 b = __floats2half2_rn(v.z, v.w);
    uint2 r;
    r.x = *(uint32_t*)&a;
    r.y = *(uint32_t*)&b;
    return r;
}

// ================= fused prep: emb convert + hist + Wp^T + 7 weight^T ===========
#define PREP_EMB_BLK  ((NIc + NUc) * 32 / 256)          // 15000
#define PREP_HIST_BLK ((EGIc + EGUc + 255) / 256)       // 3125
#define PREP_WP_BLK   ((NIc / 32) * (D / 32))           // 2500
#define PREP_WB_BLK   (4 * 4 * 7)                       // 112
#define PREP_TOTAL    (PREP_EMB_BLK + PREP_HIST_BLK + PREP_WP_BLK + PREP_WB_BLK)

__global__ void prep_kernel(const float4* __restrict__ xi, const float4* __restrict__ xu,
                            uint2* __restrict__ yi, uint2* __restrict__ yu,
                            const int* __restrict__ gi_s, const int* __restrict__ gu_s,
                            int* __restrict__ cnt_i, int* __restrict__ cnt_u,
                            const float* __restrict__ Wp, __half* __restrict__ bf,
                            const float* __restrict__ Wr1, const float* __restrict__ Wl1,
                            const float* __restrict__ Wl2, const float* __restrict__ Wr2,
                            __half* __restrict__ wt, __half* __restrict__ w1c,
                            __half* __restrict__ w2c)
{
    __shared__ float t[32][33];
    int b = blockIdx.x;
    int tid = threadIdx.x;

    if (b < PREP_EMB_BLK) {
        int i = b * 256 + tid;
        const int NI4 = NIc * 32;
        if (i < NI4) yi[i] = f4_to_h4(xi[i]);
        else         yu[i - NI4] = f4_to_h4(xu[i - NI4]);
        return;
    }
    b -= PREP_EMB_BLK;
    if (b < PREP_HIST_BLK) {
        int i = b * 256 + tid;
        if (i < EGIc) atomicAdd(cnt_i + __ldg(gi_s + i), 1);
        else if (i < EGIc + EGUc) atomicAdd(cnt_u + __ldg(gu_s + i - EGIc), 1);
        return;
    }
    b -= PREP_HIST_BLK;
    int tx = tid & 31, ty = tid >> 5;
    if (b < PREP_WP_BLK) {
        int n0 = (b % (NIc / 32)) * 32;
        int k0 = (b / (NIc / 32)) * 32;
#pragma unroll
        for (int r = ty; r < 32; r += 8)
            t[r][tx] = Wp[(size_t)(k0 + r) * NIc + n0 + tx];
        __syncthreads();
#pragma unroll
        for (int r = ty; r < 32; r += 8)
            bf[(size_t)(n0 + r) * D + k0 + tx] = __float2half_rn(t[tx][r]);
        return;
    }
    b -= PREP_WP_BLK;
    {
        int job = b >> 4;
        int cx = b & 3, cy = (b >> 2) & 3;
        const float* src = nullptr;
        const float* src2 = nullptr;
        __half* dst = nullptr;
        int ldw = 128, koff = 0;
        switch (job) {
            case 0: src = Wr1;               dst = wt;          ldw = 128; koff = 0;   break;
            case 1: src = Wr1 + 2 * D * D;   dst = wt + D * D;  ldw = 128; koff = 0;   break;
            case 2: src = Wl1 + 1 * D * D;   dst = w1c;         ldw = 256; koff = 0;   break;
            case 3: src = Wl1 + 3 * D * D;   dst = w1c;         ldw = 256; koff = 128; break;
            case 4: src = Wl2 + 1 * D * D;   dst = w2c;         ldw = 384; koff = 0;   break;
            case 5: src = Wl2 + 3 * D * D;   dst = w2c;         ldw = 384; koff = 128; break;
            default: src = Wr2 + 1 * D * D;  src2 = Wr2 + 3 * D * D; dst = w2c; ldw = 384; koff = 256; break;
        }
        int c0 = cx * 32, k0 = cy * 32;
#pragma unroll
        for (int r = ty; r < 32; r += 8) {
            float v = src[(k0 + r) * D + c0 + tx];
            if (src2) v += src2[(k0 + r) * D + c0 + tx];
            t[r][tx] = v;
        }
        __syncthreads();
#pragma unroll
        for (int r = ty; r < 32; r += 8)
            dst[(size_t)(c0 + r) * ldw + koff + k0 + tx] = __float2half_rn(t[tx][r]);
    }
}

// ================= CSR scan + fill ==============================================
__global__ void __launch_bounds__(1024, 1)
scan_kernel(const int* __restrict__ cnt_i, int* __restrict__ off_i,
            const int* __restrict__ cnt_u, int* __restrict__ off_u, int n)
{
    const int* cnt = blockIdx.x == 0 ? cnt_i : cnt_u;
    int* off = blockIdx.x == 0 ? off_i : off_u;
    __shared__ int sdata[1024];
    __shared__ int carry;
    int tid = threadIdx.x;
    if (tid == 0) carry = 0;
    __syncthreads();
    for (int base = 0; base < n; base += 1024) {
        int i = base + tid;
        int v = (i < n) ? cnt[i] : 0;
        sdata[tid] = v;
        __syncthreads();
        for (int s = 1; s < 1024; s <<= 1) {
            int t = (tid >= s) ? sdata[tid - s] : 0;
            __syncthreads();
            sdata[tid] += t;
            __syncthreads();
        }
        if (i < n) off[i] = carry + sdata[tid] - v;
        __syncthreads();
        if (tid == 1023) carry += sdata[1023];
        __syncthreads();
    }
}

__global__ void fill_kernel(const int* __restrict__ gi_s, const int* __restrict__ gi_d,
                            const int* __restrict__ gu_s, const int* __restrict__ gu_d,
                            const int* __restrict__ off_i, const int* __restrict__ off_u,
                            int* __restrict__ pos_i, int* __restrict__ pos_u,
                            int* __restrict__ nbr_i, int* __restrict__ nbr_u)
{
    int i = blockIdx.x * blockDim.x + threadIdx.x;
    if (i < EGIc) {
        int g = __ldg(gi_s + i);
        int p = atomicAdd(pos_i + g, 1);
        nbr_i[__ldg(off_i + g) + p] = __ldg(gi_d + i);
    } else if (i < EGIc + EGUc) {
        int e = i - EGIc;
        int g = __ldg(gu_s + e);
        int p = atomicAdd(pos_u + g, 1);
        nbr_u[__ldg(off_u + g) + p] = __ldg(gu_d + e);
    }
}

// ===== gather-aggregate: one warp per (group, relation); mean -> fp16 into X ====
__global__ void aggregate_kernel(const int* __restrict__ off_i, const int* __restrict__ nbr_i,
                                 const int* __restrict__ cnt_i, const uint2* __restrict__ fi,
                                 const int* __restrict__ off_u, const int* __restrict__ nbr_u,
                                 const int* __restrict__ cnt_u, const uint2* __restrict__ fu,
                                 __half* __restrict__ X, int ldx)
{
    int gw = (blockIdx.x * blockDim.x + threadIdx.x) >> 5;
    int lane = threadIdx.x & 31;
    if (gw >= 2 * NGc) return;
    bool isU = gw >= NGc;
    int g = isU ? gw - NGc : gw;
    const int* off = isU ? off_u : off_i;
    const int* nbr = isU ? nbr_u : nbr_i;
    const int* cnt = isU ? cnt_u : cnt_i;
    const uint2* f = isU ? fu : fi;

    int base = __ldg(off + g);
    int deg = __ldg(cnt + g);
    float4 acc = make_float4(0.f, 0.f, 0.f, 0.f);
    int j = 0;
    for (; j + 8 <= deg; j += 8) {
        int ii[8];
#pragma unroll
        for (int t = 0; t < 8; t++) ii[t] = __ldg(nbr + base + j + t);
        uint2 rr[8];
#pragma unroll
        for (int t = 0; t < 8; t++) rr[t] = __ldg(f + (size_t)ii[t] * 32 + lane);
#pragma unroll
        for (int t = 0; t < 8; t++) {
            float4 v = h4_to_f4(rr[t]);
            acc.x += v.x; acc.y += v.y; acc.z += v.z; acc.w += v.w;
        }
    }
    for (; j < deg; j++) {
        int i0 = __ldg(nbr + base + j);
        float4 v0 = h4_to_f4(__ldg(f + (size_t)i0 * 32 + lane));
        acc.x += v0.x; acc.y += v0.y; acc.z += v0.z; acc.w += v0.w;
    }
    float inv = 1.f / (float)max(deg, 1);
    acc.x *= inv; acc.y *= inv; acc.z *= inv; acc.w *= inv;
    *(uint2*)(X + (size_t)g * ldx + (isU ? 128 : 0) + lane * 4) = f4_to_h4(acc);
}

// ================= fp16 HMMA building blocks ====================================
__device__ __forceinline__ void mma16816(float* c, const uint32_t* a, const uint32_t* b)
{
    asm volatile(
        "mma.sync.aligned.m16n8k16.row.col.f32.f16.f16.f32 "
        "{%0,%1,%2,%3}, {%4,%5,%6,%7}, {%8,%9}, {%0,%1,%2,%3};\n"
        : "+f"(c[0]), "+f"(c[1]), "+f"(c[2]), "+f"(c[3])
        : "r"(a[0]), "r"(a[1]), "r"(a[2]), "r"(a[3]), "r"(b[0]), "r"(b[1]));
}
__device__ __forceinline__ void ldsm_x4(uint32_t* r, uint32_t addr)
{
    asm volatile("ldmatrix.sync.aligned.m8n8.x4.shared.b16 {%0,%1,%2,%3}, [%4];"
                 : "=r"(r[0]), "=r"(r[1]), "=r"(r[2]), "=r"(r[3]) : "r"(addr));
}
__device__ __forceinline__ void cp16(uint32_t dst, const void* src, bool pred)
{
    asm volatile("cp.async.ca.shared.global [%0], [%1], 16, %2;"
                 :: "r"(dst), "l"(src), "r"(pred ? 16 : 0));
}
#define CP_COMMIT() asm volatile("cp.async.commit_group;" ::: "memory")
#define CP_WAIT(n)  asm volatile("cp.async.wait_group %0;" :: "n"(n) : "memory")

#define SMSTRIDE 136   // halves per smem row (padded) — gcat
#define CSTRIDE  72    // halves per row in pipelined chunk buffers (144B)

// ------ generic: out[M,128] = relu(X[M,K] @ Wt[128,K]^T + ba + bb) in fp16 ------
__global__ void __launch_bounds__(256, 2)
gcat_gemm(const __half* __restrict__ X, int ldx, int K,
          const __half* __restrict__ Wt,
          const float* __restrict__ ba, const float* __restrict__ bb,
          __half* __restrict__ out, int ldo, int M)
{
    extern __shared__ __half sm[];
    __half* As = sm;                       // 64 x SMSTRIDE
    __half* Bs = As + 64 * SMSTRIDE;       // 128 x SMSTRIDE

    int tid = threadIdx.x;
    int m0 = blockIdx.x * 64;
    int lane = tid & 31, w = tid >> 5;
    int r = lane >> 2, c2 = (lane & 3) * 2;

    float acc[4][2][4];
#pragma unroll
    for (int i = 0; i < 4; i++)
#pragma unroll
        for (int j = 0; j < 2; j++)
#pragma unroll
            for (int q = 0; q < 4; q++) acc[i][j][q] = 0.f;

    uint4 zz = make_uint4(0, 0, 0, 0);
    for (int k0 = 0; k0 < K; k0 += 128) {
        __syncthreads();
#pragma unroll
        for (int it = 0; it < 4; it++) {
            int idx = tid + it * 256;
            int row = idx >> 4, c8 = (idx & 15) << 3;
            int gm = m0 + row;
            uint4 v = zz;
            if (gm < M) v = *(const uint4*)(X + (size_t)gm * ldx + k0 + c8);
            *(uint4*)(As + row * SMSTRIDE + c8) = v;
        }
#pragma unroll
        for (int it = 0; it < 8; it++) {
            int idx = tid + it * 256;
            int row = idx >> 4, c8 = (idx & 15) << 3;
            *(uint4*)(Bs + row * SMSTRIDE + c8) = *(const uint4*)(Wt + (size_t)row * K + k0 + c8);
        }
        __syncthreads();

#pragma unroll
        for (int ks = 0; ks < 8; ks++) {
            int kb = ks * 16 + c2;
            uint32_t a[4][4], b[2][2];
#pragma unroll
            for (int i = 0; i < 4; i++) {
                const __half* pa = As + (i * 16 + r) * SMSTRIDE + kb;
                a[i][0] = *(const uint32_t*)(pa);
                a[i][1] = *(const uint32_t*)(pa + 8 * SMSTRIDE);
                a[i][2] = *(const uint32_t*)(pa + 8);
                a[i][3] = *(const uint32_t*)(pa + 8 * SMSTRIDE + 8);
            }
#pragma unroll
            for (int j = 0; j < 2; j++) {
                const __half* pb = Bs + (w * 16 + j * 8 + r) * SMSTRIDE + kb;
                b[j][0] = *(const uint32_t*)(pb);
                b[j][1] = *(const uint32_t*)(pb + 8);
            }
#pragma unroll
            for (int i = 0; i < 4; i++)
#pragma unroll
                for (int j = 0; j < 2; j++)
                    mma16816(acc[i][j], a[i], b[j]);
        }
    }

#pragma unroll
    for (int i = 0; i < 4; i++) {
#pragma unroll
        for (int j = 0; j < 2; j++) {
            int m = m0 + i * 16 + r;
            int n = w * 16 + j * 8 + c2;
            float bx = __ldg(ba + n) + __ldg(bb + n);
            float by = __ldg(ba + n + 1) + __ldg(bb + n + 1);
            if (m < M) {
                __half2 h = __floats2half2_rn(fmaxf(acc[i][j][0] + bx, 0.f),
                                              fmaxf(acc[i][j][1] + by, 0.f));
                *(__half2*)(out + (size_t)m * ldo + n) = h;
            }
            if (m + 8 < M) {
                __half2 h = __floats2half2_rn(fmaxf(acc[i][j][2] + bx, 0.f),
                                              fmaxf(acc[i][j][3] + by, 0.f));
                *(__half2*)(out + (size_t)(m + 8) * ldo + n) = h;
            }
        }
    }
}

// ==== merged i1/u1: pipelined cp.async + ldmatrix; out = relu(X @ Wt^T + b) =====
__global__ void __launch_bounds__(256, 2)
lin_pair_gemm(const __half* __restrict__ Xi, const __half* __restrict__ Wti,
              const float* __restrict__ bi, __half* __restrict__ outi, int Mi,
              const __half* __restrict__ Xu, const __half* __restrict__ Wtu,
              const float* __restrict__ bu, __half* __restrict__ outu, int Mu)
{
    extern __shared__ __half sm[];
    int tid = threadIdx.x;
    int nbI = (Mi + 127) / 128;
    const __half* X;
    const __half* Wt;
    const float* b;
    __half* out;
    int M, m0;
    if ((int)blockIdx.x < nbI) {
        X = Xi; Wt = Wti; b = bi; out = outi; M = Mi; m0 = blockIdx.x * 128;
    } else {
        X = Xu; Wt = Wtu; b = bu; out = outu; M = Mu; m0 = (blockIdx.x - nbI) * 128;
    }

    uint32_t smb = (uint32_t)__cvta_generic_to_shared(sm);
    const uint32_t BUF = 128 * CSTRIDE * 2;

#pragma unroll
    for (int kc = 0; kc < 2; kc++) {
        uint32_t aB = smb + kc * BUF;
        uint32_t bB = smb + (2 + kc) * BUF;
#pragma unroll
        for (int it = 0; it < 4; it++) {
            int idx = tid + it * 256;
            int row = idx >> 3, c16 = idx & 7;
            int gm = m0 + row;
            bool ok = gm < M;
            const __half* src = X + (size_t)(ok ? gm : 0) * 128 + kc * 64 + c16 * 8;
            cp16(aB + row * (CSTRIDE * 2) + c16 * 16, src, ok);
        }
#pragma unroll
        for (int it = 0; it < 4; it++) {
            int idx = tid + it * 256;
            int row = idx >> 3, c16 = idx & 7;
            const __half* src = Wt + (size_t)row * 128 + kc * 64 + c16 * 8;
            cp16(bB + row * (CSTRIDE * 2) + c16 * 16, src, true);
        }
        CP_COMMIT();
    }

    int lane = tid & 31, w = tid >> 5;
    int wm = w >> 2, wn = w & 3;
    int r = lane >> 2, c2 = (lane & 3) * 2;
    int aRow = lane & 15, aKh = lane >> 4;
    int bRow = ((lane >> 4) & 1) * 8 + (lane & 7);
    int bKh = (lane >> 3) & 1;

    float acc[4][4][4];
#pragma unroll
    for (int i = 0; i < 4; i++)
#pragma unroll
        for (int j = 0; j < 4; j++)
#pragma unroll
            for (int q = 0; q < 4; q++) acc[i][j][q] = 0.f;

#pragma unroll
    for (int kc = 0; kc < 2; kc++) {
        if (kc == 0) CP_WAIT(1);
        else         CP_WAIT(0);
        __syncthreads();

        uint32_t aB = smb + kc * BUF;
        uint32_t bB = smb + (2 + kc) * BUF;
#pragma unroll
        for (int ks = 0; ks < 4; ks++) {
            uint32_t a[4][4], bb[4][2];
#pragma unroll
            for (int i = 0; i < 4; i++) {
                uint32_t addr = aB + ((wm * 64 + i * 16 + aRow) * CSTRIDE + ks * 16 + aKh * 8) * 2;
                ldsm_x4(a[i], addr);
            }
#pragma unroll
            for (int jp = 0; jp < 2; jp++) {
                uint32_t addr = bB + ((wn * 32 + jp * 16 + bRow) * CSTRIDE + ks * 16 + bKh * 8) * 2;
                uint32_t rr[4];
                ldsm_x4(rr, addr);
                bb[jp * 2][0] = rr[0]; bb[jp * 2][1] = rr[1];
                bb[jp * 2 + 1][0] = rr[2]; bb[jp * 2 + 1][1] = rr[3];
            }
#pragma unroll
            for (int i = 0; i < 4; i++)
#pragma unroll
                for (int j = 0; j < 4; j++)
                    mma16816(acc[i][j], a[i], bb[j]);
        }
        if (kc == 0) __syncthreads();
    }

#pragma unroll
    for (int i = 0; i < 4; i++) {
#pragma unroll
        for (int j = 0; j < 4; j++) {
            int m = m0 + wm * 64 + i * 16 + r;
            int n = wn * 32 + j * 8 + c2;
            float bx = __ldg(b + n), by = __ldg(b + n + 1);
            if (m < M) {
                __half2 h = __floats2half2_rn(fmaxf(acc[i][j][0] + bx, 0.f),
                                              fmaxf(acc[i][j][1] + by, 0.f));
                __stcs((__half2*)(out + (size_t)m * 128 + n), h);
            }
            if (m + 8 < M) {
                __half2 h = __floats2half2_rn(fmaxf(acc[i][j][2] + bx, 0.f),
                                              fmaxf(acc[i][j][3] + by, 0.f));
                __stcs((__half2*)(out + (size_t)(m + 8) * 128 + n), h);
            }
        }
    }
}

// ====== final GEMM: cp.async double-buffered K-split + ldmatrix fragments =======
__global__ void __launch_bounds__(256, 2)
gemm_f16(const __half* __restrict__ A, const __half* __restrict__ B,
         const float* __restrict__ bias, float* __restrict__ C, int M, int N)
{
    extern __shared__ __half sm[];
    int tid = threadIdx.x;
    int m0 = blockIdx.y * 128, n0 = blockIdx.x * 128;
    uint32_t smb = (uint32_t)__cvta_generic_to_shared(sm);
    const uint32_t BUF = 128 * CSTRIDE * 2;

#pragma unroll
    for (int kc = 0; kc < 2; kc++) {
        uint32_t aB = smb + kc * BUF;
        uint32_t bB = smb + (2 + kc) * BUF;
#pragma unroll
        for (int it = 0; it < 4; it++) {
            int idx = tid + it * 256;
            int row = idx >> 3, c16 = idx & 7;
            int gm = m0 + row;
            bool ok = gm < M;
            const __half* src = A + (size_t)(ok ? gm : 0) * 128 + kc * 64 + c16 * 8;
            cp16(aB + row * (CSTRIDE * 2) + c16 * 16, src, ok);
        }
#pragma unroll
        for (int it = 0; it < 4; it++) {
            int idx = tid + it * 256;
            int row = idx >> 3, c16 = idx & 7;
            int gn = n0 + row;
            bool ok = gn < N;
            const __half* src = B + (size_t)(ok ? gn : 0) * 128 + kc * 64 + c16 * 8;
            cp16(bB + row * (CSTRIDE * 2) + c16 * 16, src, ok);
        }
        CP_COMMIT();
    }

    int lane = tid & 31, w = tid >> 5;
    int wm = w >> 2, wn = w & 3;
    int r = lane >> 2, c2 = (lane & 3) * 2;
    int aRow = lane & 15, aKh = lane >> 4;
    int bRow = ((lane >> 4) & 1) * 8 + (lane & 7);
    int bKh = (lane >> 3) & 1;

    float acc[4][4][4];
#pragma unroll
    for (int i = 0; i < 4; i++)
#pragma unroll
        for (int j = 0; j < 4; j++)
#pragma unroll
            for (int q = 0; q < 4; q++) acc[i][j][q] = 0.f;

#pragma unroll
    for (int kc = 0; kc < 2; kc++) {
        if (kc == 0) CP_WAIT(1);
        else         CP_WAIT(0);
        __syncthreads();

        uint32_t aB = smb + kc * BUF;
        uint32_t bB = smb + (2 + kc) * BUF;
#pragma unroll
        for (int ks = 0; ks < 4; ks++) {
            uint32_t a[4][4], b[4][2];
#pragma unroll
            for (int i = 0; i < 4; i++) {
                uint32_t addr = aB + ((wm * 64 + i * 16 + aRow) * CSTRIDE + ks * 16 + aKh * 8) * 2;
                ldsm_x4(a[i], addr);
            }
#pragma unroll
            for (int jp = 0; jp < 2; jp++) {
                uint32_t addr = bB + ((wn * 32 + jp * 16 + bRow) * CSTRIDE + ks * 16 + bKh * 8) * 2;
                uint32_t rr[4];
                ldsm_x4(rr, addr);
                b[jp * 2][0] = rr[0]; b[jp * 2][1] = rr[1];
                b[jp * 2 + 1][0] = rr[2]; b[jp * 2 + 1][1] = rr[3];
            }
#pragma unroll
            for (int i = 0; i < 4; i++)
#pragma unroll
                for (int j = 0; j < 4; j++)
                    mma16816(acc[i][j], a[i], b[j]);
        }
        if (kc == 0) __syncthreads();
    }

#pragma unroll
    for (int i = 0; i < 4; i++) {
#pragma unroll
        for (int j = 0; j < 4; j++) {
            int m = m0 + wm * 64 + i * 16 + r;
            int n = n0 + wn * 32 + j * 8 + c2;
            if (n < N) {
                float bx = __ldg(bias + n), by = __ldg(bias + n + 1);
                if (m < M) {
                    float2 o = make_float2(acc[i][j][0] + bx, acc[i][j][1] + by);
                    __stcs((float2*)(C + (size_t)m * N + n), o);
                }
                if (m + 8 < M) {
                    float2 o = make_float2(acc[i][j][2] + bx, acc[i][j][3] + by);
                    __stcs((float2*)(C + (size_t)(m + 8) * N + n), o);
                }
            }
        }
    }
}

// ------------------------------ launcher ----------------------------------------
extern "C" void kernel_launch(void* const* d_in, const int* in_sizes, int n_in,
                              void* d_out, int out_size)
{
    const int*   gi_src  = (const int*)d_in[3];
    const int*   gi_dst  = (const int*)d_in[4];
    const int*   gu_src  = (const int*)d_in[5];
    const int*   gu_dst  = (const int*)d_in[6];
    const float* emb_u   = (const float*)d_in[8];
    const float* emb_i   = (const float*)d_in[9];
    const float* Wl1     = (const float*)d_in[10];
    const float* Wr1     = (const float*)d_in[11];
    const float* b1      = (const float*)d_in[12];
    const float* Wl2     = (const float*)d_in[13];
    const float* Wr2     = (const float*)d_in[14];
    const float* b2      = (const float*)d_in[15];
    const float* Wp      = (const float*)d_in[16];
    const float* bp      = (const float*)d_in[17];
    float*       out     = (float*)d_out;

    ZeroRegion* zr;
    int *off_i, *off_u, *nbr_i, *nbr_u;
    __half *embih, *embuh, *wt, *w1c, *w2c, *x1, *x2, *i1h, *u1h, *af, *bf;
    cudaGetSymbolAddress((void**)&zr,     g_zr);
    cudaGetSymbolAddress((void**)&off_i,  g_off_i);
    cudaGetSymbolAddress((void**)&off_u,  g_off_u);
    cudaGetSymbolAddress((void**)&nbr_i,  g_nbr_i);
    cudaGetSymbolAddress((void**)&nbr_u,  g_nbr_u);
    cudaGetSymbolAddress((void**)&embih,  g_embih);
    cudaGetSymbolAddress((void**)&embuh,  g_embuh);
    cudaGetSymbolAddress((void**)&wt,     g_Wt);
    cudaGetSymbolAddress((void**)&w1c,    g_W1c);
    cudaGetSymbolAddress((void**)&w2c,    g_W2c);
    cudaGetSymbolAddress((void**)&x1,     g_X1);
    cudaGetSymbolAddress((void**)&x2,     g_X2);
    cudaGetSymbolAddress((void**)&i1h,    g_i1h);
    cudaGetSymbolAddress((void**)&u1h,    g_u1h);
    cudaGetSymbolAddress((void**)&af,     g_Af);
    cudaGetSymbolAddress((void**)&bf,     g_Bf);

    int* cnt_i = zr->cnt_i;
    int* cnt_u = zr->cnt_u;
    int* pos_i = zr->pos_i;
    int* pos_u = zr->pos_u;

    cudaMemsetAsync(zr, 0, sizeof(ZeroRegion));

    int smemGcat = (64 + 128) * SMSTRIDE * sizeof(__half);
    int smemPipe = 4 * 128 * CSTRIDE * sizeof(__half);   // 73728
    cudaFuncSetAttribute(lin_pair_gemm, cudaFuncAttributeMaxDynamicSharedMemorySize, smemPipe);
    cudaFuncSetAttribute(gemm_f16,      cudaFuncAttributeMaxDynamicSharedMemorySize, smemPipe);
    cudaFuncSetAttribute(gcat_gemm,     cudaFuncAttributeMaxDynamicSharedMemorySize, smemGcat);

    // side stream + events for capture-legal fork/join (host objects; no device mem)
    cudaStream_t s2;
    cudaStreamCreateWithFlags(&s2, cudaStreamNonBlocking);
    cudaEvent_t evPrep, evLin;
    cudaEventCreateWithFlags(&evPrep, cudaEventDisableTiming);
    cudaEventCreateWithFlags(&evLin,  cudaEventDisableTiming);

    // fused prep: emb->fp16, edge histogram, Wp^T, 7 weight transposes
    prep_kernel<<<PREP_TOTAL, 256>>>((const float4*)emb_i, (const float4*)emb_u,
                                     (uint2*)embih, (uint2*)embuh,
                                     gi_src, gu_src, cnt_i, cnt_u,
                                     Wp, bf, Wr1, Wl1, Wl2, Wr2, wt, w1c, w2c);
    cudaEventRecord(evPrep, 0);

    // side stream: i1/u1 GEMM concurrent with the CSR/aggregate chain
    cudaStreamWaitEvent(s2, evPrep, 0);
    int nbI = (NIc + 127) / 128, nbU = (NUc + 127) / 128;
    lin_pair_gemm<<<nbI + nbU, 256, smemPipe, s2>>>(embih, wt, b1 + 0 * D, i1h, NIc,
                                                    embuh, wt + D * D, b1 + 2 * D, u1h, NUc);
    cudaEventRecord(evLin, s2);

    // main stream: CSR scan + fill, layer-1 aggregate, g1
    scan_kernel<<<2, 1024>>>(cnt_i, off_i, cnt_u, off_u, NGc);
    fill_kernel<<<(EGIc + EGUc + 255) / 256, 256>>>(gi_src, gi_dst, gu_src, gu_dst,
                                                    off_i, off_u, pos_i, pos_u, nbr_i, nbr_u);
    aggregate_kernel<<<(2 * NGc * 32 + 255) / 256, 256>>>(off_i, nbr_i, cnt_i, (const uint2*)embih,
                                                          off_u, nbr_u, cnt_u, (const uint2*)embuh,
                                                          x1, 256);
    gcat_gemm<<<(NGc + 63) / 64, 256, smemGcat>>>(x1, 256, 256, w1c,
                                                  b1 + 1 * D, b1 + 3 * D, x2 + 256, 384, NGc);

    // join: layer-2 aggregate needs i1h/u1h
    cudaStreamWaitEvent(0, evLin, 0);
    aggregate_kernel<<<(2 * NGc * 32 + 255) / 256, 256>>>(off_i, nbr_i, cnt_i, (const uint2*)i1h,
                                                          off_u, nbr_u, cnt_u, (const uint2*)u1h,
                                                          x2, 384);
    gcat_gemm<<<(NGc + 63) / 64, 256, smemGcat>>>(x2, 384, 384, w2c,
                                                  b2 + 1 * D, b2 + 3 * D, af, 128, NGc);

    // out = g2 @ WpT^T + bp  via pipelined fp16 tensor GEMM
    dim3 grid((NIc + 127) / 128, (NGc + 127) / 128);
    gemm_f16<<<grid, 256, smemPipe>>>(af, bf, bp, out, NGc, NIc);
}

// round 15
// speedup vs baseline: 1.4608x; 1.4608x over previous
#include <cuda_runtime.h>
#include <cuda_fp16.h>
#include <cstdint>

#define D    128
#define NGc  10000
#define NUc  100000
#define NIc  20000
#define EGIc 400000
#define EGUc 400000

// ---------------- scratch (device globals; no allocation allowed) -------------
struct ZeroRegion {
    int cnt_i[NGc];
    int cnt_u[NGc];
    int pos_i[NGc];
    int pos_u[NGc];
};
__device__ ZeroRegion g_zr;

__device__ int    g_off_i[NGc];
__device__ int    g_off_u[NGc];
__device__ int    g_nbr_i[EGIc];
__device__ int    g_nbr_u[EGUc];
__device__ __half g_embih[NIc * D];
__device__ __half g_embuh[NUc * D];
__device__ __half g_Wt[2 * D * D];      // Wr1[0]^T, Wr1[2]^T fp16
__device__ __half g_W1c[D * 256];       // [Wl1[1];Wl1[3]]^T
__device__ __half g_W2c[D * 384];       // [Wl2[1];Wl2[3];Wr2[1]+Wr2[3]]^T
__device__ __half g_X1[NGc * 256];      // [aggI, aggU] fp16
__device__ __half g_X2[NGc * 384];      // [agg2I, agg2U, g1] fp16
__device__ __half g_i1h[NIc * D];
__device__ __half g_u1h[NUc * D];
__device__ __half g_Af[NGc * D];        // g2 fp16
__device__ __half g_Bf[NIc * D];        // WpT fp16: [n][k]

// ---------------- helpers -------------------------------------------------------
__device__ __forceinline__ float4 h4_to_f4(uint2 r)
{
    __half2 a = *(__half2*)&r.x;
    __half2 b = *(__half2*)&r.y;
    float2 fa = __half22float2(a), fb = __half22float2(b);
    return make_float4(fa.x, fa.y, fb.x, fb.y);
}
__device__ __forceinline__ uint2 f4_to_h4(float4 v)
{
    __half2 a = __floats2half2_rn(v.x, v.y);
    __half2 b = __floats2half2_rn(v.z, v.w);
    uint2 r;
    r.x = *(uint32_t*)&a;
    r.y = *(uint32_t*)&b;
    return r;
}

// ================= fused prep: emb convert + hist + Wp^T + 7 weight^T ===========
// hist section: 4 grid-strided edges per thread (stride = HIST_THREADS)
#define PREP_EMB_BLK  ((NIc + NUc) * 32 / 256)                // 15000
#define HIST_THREADS  ((EGIc + EGUc + 3) / 4)                 // 200000
#define PREP_HIST_BLK ((HIST_THREADS + 255) / 256)            // 782
#define PREP_WP_BLK   ((NIc / 32) * (D / 32))                 // 2500
#define PREP_WB_BLK   (4 * 4 * 7)                             // 112
#define PREP_TOTAL    (PREP_EMB_BLK + PREP_HIST_BLK + PREP_WP_BLK + PREP_WB_BLK)

__global__ void prep_kernel(const float4* __restrict__ xi, const float4* __restrict__ xu,
                            uint2* __restrict__ yi, uint2* __restrict__ yu,
                            const int* __restrict__ gi_s, const int* __restrict__ gu_s,
                            int* __restrict__ cnt_i, int* __restrict__ cnt_u,
                            const float* __restrict__ Wp, __half* __restrict__ bf,
                            const float* __restrict__ Wr1, const float* __restrict__ Wl1,
                            const float* __restrict__ Wl2, const float* __restrict__ Wr2,
                            __half* __restrict__ wt, __half* __restrict__ w1c,
                            __half* __restrict__ w2c)
{
    __shared__ float t[32][33];
    int b = blockIdx.x;
    int tid = threadIdx.x;

    if (b < PREP_EMB_BLK) {
        int i = b * 256 + tid;
        const int NI4 = NIc * 32;
        if (i < NI4) yi[i] = f4_to_h4(xi[i]);
        else         yu[i - NI4] = f4_to_h4(xu[i - NI4]);
        return;
    }
    b -= PREP_EMB_BLK;
    if (b < PREP_HIST_BLK) {
        int base = b * 256 + tid;
        if (base < HIST_THREADS) {          // guard: stride == HIST_THREADS exactly
#pragma unroll
            for (int q = 0; q < 4; q++) {
                int i = base + q * HIST_THREADS;
                if (i < EGIc) atomicAdd(cnt_i + __ldg(gi_s + i), 1);
                else if (i < EGIc + EGUc) atomicAdd(cnt_u + __ldg(gu_s + i - EGIc), 1);
            }
        }
        return;
    }
    b -= PREP_HIST_BLK;
    int tx = tid & 31, ty = tid >> 5;
    if (b < PREP_WP_BLK) {
        int n0 = (b % (NIc / 32)) * 32;
        int k0 = (b / (NIc / 32)) * 32;
#pragma unroll
        for (int r = ty; r < 32; r += 8)
            t[r][tx] = Wp[(size_t)(k0 + r) * NIc + n0 + tx];
        __syncthreads();
#pragma unroll
        for (int r = ty; r < 32; r += 8)
            bf[(size_t)(n0 + r) * D + k0 + tx] = __float2half_rn(t[tx][r]);
        return;
    }
    b -= PREP_WP_BLK;
    {
        int job = b >> 4;
        int cx = b & 3, cy = (b >> 2) & 3;
        const float* src = nullptr;
        const float* src2 = nullptr;
        __half* dst = nullptr;
        int ldw = 128, koff = 0;
        switch (job) {
            case 0: src = Wr1;               dst = wt;          ldw = 128; koff = 0;   break;
            case 1: src = Wr1 + 2 * D * D;   dst = wt + D * D;  ldw = 128; koff = 0;   break;
            case 2: src = Wl1 + 1 * D * D;   dst = w1c;         ldw = 256; koff = 0;   break;
            case 3: src = Wl1 + 3 * D * D;   dst = w1c;         ldw = 256; koff = 128; break;
            case 4: src = Wl2 + 1 * D * D;   dst = w2c;         ldw = 384; koff = 0;   break;
            case 5: src = Wl2 + 3 * D * D;   dst = w2c;         ldw = 384; koff = 128; break;
            default: src = Wr2 + 1 * D * D;  src2 = Wr2 + 3 * D * D; dst = w2c; ldw = 384; koff = 256; break;
        }
        int c0 = cx * 32, k0 = cy * 32;
#pragma unroll
        for (int r = ty; r < 32; r += 8) {
            float v = src[(k0 + r) * D + c0 + tx];
            if (src2) v += src2[(k0 + r) * D + c0 + tx];
            t[r][tx] = v;
        }
        __syncthreads();
#pragma unroll
        for (int r = ty; r < 32; r += 8)
            dst[(size_t)(c0 + r) * ldw + koff + k0 + tx] = __float2half_rn(t[tx][r]);
    }
}

// ================= CSR scan + fill ==============================================
__global__ void __launch_bounds__(1024, 1)
scan_kernel(const int* __restrict__ cnt_i, int* __restrict__ off_i,
            const int* __restrict__ cnt_u, int* __restrict__ off_u, int n)
{
    const int* cnt = blockIdx.x == 0 ? cnt_i : cnt_u;
    int* off = blockIdx.x == 0 ? off_i : off_u;
    __shared__ int sdata[1024];
    __shared__ int carry;
    int tid = threadIdx.x;
    if (tid == 0) carry = 0;
    __syncthreads();
    for (int base = 0; base < n; base += 1024) {
        int i = base + tid;
        int v = (i < n) ? cnt[i] : 0;
        sdata[tid] = v;
        __syncthreads();
        for (int s = 1; s < 1024; s <<= 1) {
            int t = (tid >= s) ? sdata[tid - s] : 0;
            __syncthreads();
            sdata[tid] += t;
            __syncthreads();
        }
        if (i < n) off[i] = carry + sdata[tid] - v;
        __syncthreads();
        if (tid == 1023) carry += sdata[1023];
        __syncthreads();
    }
}

// fill: 4 grid-strided edges per thread (stride = HIST_THREADS), guarded
__global__ void fill_kernel(const int* __restrict__ gi_s, const int* __restrict__ gi_d,
                            const int* __restrict__ gu_s, const int* __restrict__ gu_d,
                            const int* __restrict__ off_i, const int* __restrict__ off_u,
                            int* __restrict__ pos_i, int* __restrict__ pos_u,
                            int* __restrict__ nbr_i, int* __restrict__ nbr_u)
{
    int base = blockIdx.x * blockDim.x + threadIdx.x;
    if (base >= HIST_THREADS) return;       // guard: stride == HIST_THREADS exactly
#pragma unroll
    for (int q = 0; q < 4; q++) {
        int i = base + q * HIST_THREADS;
        if (i < EGIc) {
            int g = __ldg(gi_s + i);
            int p = atomicAdd(pos_i + g, 1);
            nbr_i[__ldg(off_i + g) + p] = __ldg(gi_d + i);
        } else if (i < EGIc + EGUc) {
            int e = i - EGIc;
            int g = __ldg(gu_s + e);
            int p = atomicAdd(pos_u + g, 1);
            nbr_u[__ldg(off_u + g) + p] = __ldg(gu_d + e);
        }
    }
}

// ===== gather-aggregate: one warp per (group, relation); mean -> fp16 into X ====
__global__ void aggregate_kernel(const int* __restrict__ off_i, const int* __restrict__ nbr_i,
                                 const int* __restrict__ cnt_i, const uint2* __restrict__ fi,
                                 const int* __restrict__ off_u, const int* __restrict__ nbr_u,
                                 const int* __restrict__ cnt_u, const uint2* __restrict__ fu,
                                 __half* __restrict__ X, int ldx)
{
    int gw = (blockIdx.x * blockDim.x + threadIdx.x) >> 5;
    int lane = threadIdx.x & 31;
    if (gw >= 2 * NGc) return;
    bool isU = gw >= NGc;
    int g = isU ? gw - NGc : gw;
    const int* off = isU ? off_u : off_i;
    const int* nbr = isU ? nbr_u : nbr_i;
    const int* cnt = isU ? cnt_u : cnt_i;
    const uint2* f = isU ? fu : fi;

    int base = __ldg(off + g);
    int deg = __ldg(cnt + g);
    float4 acc = make_float4(0.f, 0.f, 0.f, 0.f);
    int j = 0;
    for (; j + 8 <= deg; j += 8) {
        int ii[8];
#pragma unroll
        for (int t = 0; t < 8; t++) ii[t] = __ldg(nbr + base + j + t);
        uint2 rr[8];
#pragma unroll
        for (int t = 0; t < 8; t++) rr[t] = __ldg(f + (size_t)ii[t] * 32 + lane);
#pragma unroll
        for (int t = 0; t < 8; t++) {
            float4 v = h4_to_f4(rr[t]);
            acc.x += v.x; acc.y += v.y; acc.z += v.z; acc.w += v.w;
        }
    }
    for (; j < deg; j++) {
        int i0 = __ldg(nbr + base + j);
        float4 v0 = h4_to_f4(__ldg(f + (size_t)i0 * 32 + lane));
        acc.x += v0.x; acc.y += v0.y; acc.z += v0.z; acc.w += v0.w;
    }
    float inv = 1.f / (float)max(deg, 1);
    acc.x *= inv; acc.y *= inv; acc.z *= inv; acc.w *= inv;
    *(uint2*)(X + (size_t)g * ldx + (isU ? 128 : 0) + lane * 4) = f4_to_h4(acc);
}

// ================= fp16 HMMA building blocks ====================================
__device__ __forceinline__ void mma16816(float* c, const uint32_t* a, const uint32_t* b)
{
    asm volatile(
        "mma.sync.aligned.m16n8k16.row.col.f32.f16.f16.f32 "
        "{%0,%1,%2,%3}, {%4,%5,%6,%7}, {%8,%9}, {%0,%1,%2,%3};\n"
        : "+f"(c[0]), "+f"(c[1]), "+f"(c[2]), "+f"(c[3])
        : "r"(a[0]), "r"(a[1]), "r"(a[2]), "r"(a[3]), "r"(b[0]), "r"(b[1]));
}
__device__ __forceinline__ void ldsm_x4(uint32_t* r, uint32_t addr)
{
    asm volatile("ldmatrix.sync.aligned.m8n8.x4.shared.b16 {%0,%1,%2,%3}, [%4];"
                 : "=r"(r[0]), "=r"(r[1]), "=r"(r[2]), "=r"(r[3]) : "r"(addr));
}
__device__ __forceinline__ void cp16(uint32_t dst, const void* src, bool pred)
{
    asm volatile("cp.async.ca.shared.global [%0], [%1], 16, %2;"
                 :: "r"(dst), "l"(src), "r"(pred ? 16 : 0));
}
#define CP_COMMIT() asm volatile("cp.async.commit_group;" ::: "memory")
#define CP_WAIT(n)  asm volatile("cp.async.wait_group %0;" :: "n"(n) : "memory")

#define SMSTRIDE 136   // halves per smem row (padded) — gcat
#define CSTRIDE  72    // halves per row in pipelined chunk buffers (144B)

// ------ generic: out[M,128] = relu(X[M,K] @ Wt[128,K]^T + ba + bb) in fp16 ------
__global__ void __launch_bounds__(256, 2)
gcat_gemm(const __half* __restrict__ X, int ldx, int K,
          const __half* __restrict__ Wt,
          const float* __restrict__ ba, const float* __restrict__ bb,
          __half* __restrict__ out, int ldo, int M)
{
    extern __shared__ __half sm[];
    __half* As = sm;                       // 64 x SMSTRIDE
    __half* Bs = As + 64 * SMSTRIDE;       // 128 x SMSTRIDE

    int tid = threadIdx.x;
    int m0 = blockIdx.x * 64;
    int lane = tid & 31, w = tid >> 5;
    int r = lane >> 2, c2 = (lane & 3) * 2;

    float acc[4][2][4];
#pragma unroll
    for (int i = 0; i < 4; i++)
#pragma unroll
        for (int j = 0; j < 2; j++)
#pragma unroll
            for (int q = 0; q < 4; q++) acc[i][j][q] = 0.f;

    uint4 zz = make_uint4(0, 0, 0, 0);
    for (int k0 = 0; k0 < K; k0 += 128) {
        __syncthreads();
#pragma unroll
        for (int it = 0; it < 4; it++) {
            int idx = tid + it * 256;
            int row = idx >> 4, c8 = (idx & 15) << 3;
            int gm = m0 + row;
            uint4 v = zz;
            if (gm < M) v = *(const uint4*)(X + (size_t)gm * ldx + k0 + c8);
            *(uint4*)(As + row * SMSTRIDE + c8) = v;
        }
#pragma unroll
        for (int it = 0; it < 8; it++) {
            int idx = tid + it * 256;
            int row = idx >> 4, c8 = (idx & 15) << 3;
            *(uint4*)(Bs + row * SMSTRIDE + c8) = *(const uint4*)(Wt + (size_t)row * K + k0 + c8);
        }
        __syncthreads();

#pragma unroll
        for (int ks = 0; ks < 8; ks++) {
            int kb = ks * 16 + c2;
            uint32_t a[4][4], b[2][2];
#pragma unroll
            for (int i = 0; i < 4; i++) {
                const __half* pa = As + (i * 16 + r) * SMSTRIDE + kb;
                a[i][0] = *(const uint32_t*)(pa);
                a[i][1] = *(const uint32_t*)(pa + 8 * SMSTRIDE);
                a[i][2] = *(const uint32_t*)(pa + 8);
                a[i][3] = *(const uint32_t*)(pa + 8 * SMSTRIDE + 8);
            }
#pragma unroll
            for (int j = 0; j < 2; j++) {
                const __half* pb = Bs + (w * 16 + j * 8 + r) * SMSTRIDE + kb;
                b[j][0] = *(const uint32_t*)(pb);
                b[j][1] = *(const uint32_t*)(pb + 8);
            }
#pragma unroll
            for (int i = 0; i < 4; i++)
#pragma unroll
                for (int j = 0; j < 2; j++)
                    mma16816(acc[i][j], a[i], b[j]);
        }
    }

#pragma unroll
    for (int i = 0; i < 4; i++) {
#pragma unroll
        for (int j = 0; j < 2; j++) {
            int m = m0 + i * 16 + r;
            int n = w * 16 + j * 8 + c2;
            float bx = __ldg(ba + n) + __ldg(bb + n);
            float by = __ldg(ba + n + 1) + __ldg(bb + n + 1);
            if (m < M) {
                __half2 h = __floats2half2_rn(fmaxf(acc[i][j][0] + bx, 0.f),
                                              fmaxf(acc[i][j][1] + by, 0.f));
                *(__half2*)(out + (size_t)m * ldo + n) = h;
            }
            if (m + 8 < M) {
                __half2 h = __floats2half2_rn(fmaxf(acc[i][j][2] + bx, 0.f),
                                              fmaxf(acc[i][j][3] + by, 0.f));
                *(__half2*)(out + (size_t)(m + 8) * ldo + n) = h;
            }
        }
    }
}

// ==== merged i1/u1: pipelined cp.async + ldmatrix; out = relu(X @ Wt^T + b) =====
__global__ void __launch_bounds__(256, 2)
lin_pair_gemm(const __half* __restrict__ Xi, const __half* __restrict__ Wti,
              const float* __restrict__ bi, __half* __restrict__ outi, int Mi,
              const __half* __restrict__ Xu, const __half* __restrict__ Wtu,
              const float* __restrict__ bu, __half* __restrict__ outu, int Mu)
{
    extern __shared__ __half sm[];
    int tid = threadIdx.x;
    int nbI = (Mi + 127) / 128;
    const __half* X;
    const __half* Wt;
    const float* b;
    __half* out;
    int M, m0;
    if ((int)blockIdx.x < nbI) {
        X = Xi; Wt = Wti; b = bi; out = outi; M = Mi; m0 = blockIdx.x * 128;
    } else {
        X = Xu; Wt = Wtu; b = bu; out = outu; M = Mu; m0 = (blockIdx.x - nbI) * 128;
    }

    uint32_t smb = (uint32_t)__cvta_generic_to_shared(sm);
    const uint32_t BUF = 128 * CSTRIDE * 2;

#pragma unroll
    for (int kc = 0; kc < 2; kc++) {
        uint32_t aB = smb + kc * BUF;
        uint32_t bB = smb + (2 + kc) * BUF;
#pragma unroll
        for (int it = 0; it < 4; it++) {
            int idx = tid + it * 256;
            int row = idx >> 3, c16 = idx & 7;
            int gm = m0 + row;
            bool ok = gm < M;
            const __half* src = X + (size_t)(ok ? gm : 0) * 128 + kc * 64 + c16 * 8;
            cp16(aB + row * (CSTRIDE * 2) + c16 * 16, src, ok);
        }
#pragma unroll
        for (int it = 0; it < 4; it++) {
            int idx = tid + it * 256;
            int row = idx >> 3, c16 = idx & 7;
            const __half* src = Wt + (size_t)row * 128 + kc * 64 + c16 * 8;
            cp16(bB + row * (CSTRIDE * 2) + c16 * 16, src, true);
        }
        CP_COMMIT();
    }

    int lane = tid & 31, w = tid >> 5;
    int wm = w >> 2, wn = w & 3;
    int r = lane >> 2, c2 = (lane & 3) * 2;
    int aRow = lane & 15, aKh = lane >> 4;
    int bRow = ((lane >> 4) & 1) * 8 + (lane & 7);
    int bKh = (lane >> 3) & 1;

    float acc[4][4][4];
#pragma unroll
    for (int i = 0; i < 4; i++)
#pragma unroll
        for (int j = 0; j < 4; j++)
#pragma unroll
            for (int q = 0; q < 4; q++) acc[i][j][q] = 0.f;

#pragma unroll
    for (int kc = 0; kc < 2; kc++) {
        if (kc == 0) CP_WAIT(1);
        else         CP_WAIT(0);
        __syncthreads();

        uint32_t aB = smb + kc * BUF;
        uint32_t bB = smb + (2 + kc) * BUF;
#pragma unroll
        for (int ks = 0; ks < 4; ks++) {
            uint32_t a[4][4], bb[4][2];
#pragma unroll
            for (int i = 0; i < 4; i++) {
                uint32_t addr = aB + ((wm * 64 + i * 16 + aRow) * CSTRIDE + ks * 16 + aKh * 8) * 2;
                ldsm_x4(a[i], addr);
            }
#pragma unroll
            for (int jp = 0; jp < 2; jp++) {
                uint32_t addr = bB + ((wn * 32 + jp * 16 + bRow) * CSTRIDE + ks * 16 + bKh * 8) * 2;
                uint32_t rr[4];
                ldsm_x4(rr, addr);
                bb[jp * 2][0] = rr[0]; bb[jp * 2][1] = rr[1];
                bb[jp * 2 + 1][0] = rr[2]; bb[jp * 2 + 1][1] = rr[3];
            }
#pragma unroll
            for (int i = 0; i < 4; i++)
#pragma unroll
                for (int j = 0; j < 4; j++)
                    mma16816(acc[i][j], a[i], bb[j]);
        }
        if (kc == 0) __syncthreads();
    }

#pragma unroll
    for (int i = 0; i < 4; i++) {
#pragma unroll
        for (int j = 0; j < 4; j++) {
            int m = m0 + wm * 64 + i * 16 + r;
            int n = wn * 32 + j * 8 + c2;
            float bx = __ldg(b + n), by = __ldg(b + n + 1);
            if (m < M) {
                __half2 h = __floats2half2_rn(fmaxf(acc[i][j][0] + bx, 0.f),
                                              fmaxf(acc[i][j][1] + by, 0.f));
                __stcs((__half2*)(out + (size_t)m * 128 + n), h);
            }
            if (m + 8 < M) {
                __half2 h = __floats2half2_rn(fmaxf(acc[i][j][2] + bx, 0.f),
                                              fmaxf(acc[i][j][3] + by, 0.f));
                __stcs((__half2*)(out + (size_t)(m + 8) * 128 + n), h);
            }
        }
    }
}

// ====== final GEMM: cp.async double-buffered K-split + ldmatrix fragments =======
__global__ void __launch_bounds__(256, 2)
gemm_f16(const __half* __restrict__ A, const __half* __restrict__ B,
         const float* __restrict__ bias, float* __restrict__ C, int M, int N)
{
    extern __shared__ __half sm[];
    int tid = threadIdx.x;
    int m0 = blockIdx.y * 128, n0 = blockIdx.x * 128;
    uint32_t smb = (uint32_t)__cvta_generic_to_shared(sm);
    const uint32_t BUF = 128 * CSTRIDE * 2;

#pragma unroll
    for (int kc = 0; kc < 2; kc++) {
        uint32_t aB = smb + kc * BUF;
        uint32_t bB = smb + (2 + kc) * BUF;
#pragma unroll
        for (int it = 0; it < 4; it++) {
            int idx = tid + it * 256;
            int row = idx >> 3, c16 = idx & 7;
            int gm = m0 + row;
            bool ok = gm < M;
            const __half* src = A + (size_t)(ok ? gm : 0) * 128 + kc * 64 + c16 * 8;
            cp16(aB + row * (CSTRIDE * 2) + c16 * 16, src, ok);
        }
#pragma unroll
        for (int it = 0; it < 4; it++) {
            int idx = tid + it * 256;
            int row = idx >> 3, c16 = idx & 7;
            int gn = n0 + row;
            bool ok = gn < N;
            const __half* src = B + (size_t)(ok ? gn : 0) * 128 + kc * 64 + c16 * 8;
            cp16(bB + row * (CSTRIDE * 2) + c16 * 16, src, ok);
        }
        CP_COMMIT();
    }

    int lane = tid & 31, w = tid >> 5;
    int wm = w >> 2, wn = w & 3;
    int r = lane >> 2, c2 = (lane & 3) * 2;
    int aRow = lane & 15, aKh = lane >> 4;
    int bRow = ((lane >> 4) & 1) * 8 + (lane & 7);
    int bKh = (lane >> 3) & 1;

    float acc[4][4][4];
#pragma unroll
    for (int i = 0; i < 4; i++)
#pragma unroll
        for (int j = 0; j < 4; j++)
#pragma unroll
            for (int q = 0; q < 4; q++) acc[i][j][q] = 0.f;

#pragma unroll
    for (int kc = 0; kc < 2; kc++) {
        if (kc == 0) CP_WAIT(1);
        else         CP_WAIT(0);
        __syncthreads();

        uint32_t aB = smb + kc * BUF;
        uint32_t bB = smb + (2 + kc) * BUF;
#pragma unroll
        for (int ks = 0; ks < 4; ks++) {
            uint32_t a[4][4], b[4][2];
#pragma unroll
            for (int i = 0; i < 4; i++) {
                uint32_t addr = aB + ((wm * 64 + i * 16 + aRow) * CSTRIDE + ks * 16 + aKh * 8) * 2;
                ldsm_x4(a[i], addr);
            }
#pragma unroll
            for (int jp = 0; jp < 2; jp++) {
                uint32_t addr = bB + ((wn * 32 + jp * 16 + bRow) * CSTRIDE + ks * 16 + bKh * 8) * 2;
                uint32_t rr[4];
                ldsm_x4(rr, addr);
                b[jp * 2][0] = rr[0]; b[jp * 2][1] = rr[1];
                b[jp * 2 + 1][0] = rr[2]; b[jp * 2 + 1][1] = rr[3];
            }
#pragma unroll
            for (int i = 0; i < 4; i++)
#pragma unroll
                for (int j = 0; j < 4; j++)
                    mma16816(acc[i][j], a[i], b[j]);
        }
        if (kc == 0) __syncthreads();
    }

#pragma unroll
    for (int i = 0; i < 4; i++) {
#pragma unroll
        for (int j = 0; j < 4; j++) {
            int m = m0 + wm * 64 + i * 16 + r;
            int n = n0 + wn * 32 + j * 8 + c2;
            if (n < N) {
                float bx = __ldg(bias + n), by = __ldg(bias + n + 1);
                if (m < M) {
                    float2 o = make_float2(acc[i][j][0] + bx, acc[i][j][1] + by);
                    __stcs((float2*)(C + (size_t)m * N + n), o);
                }
                if (m + 8 < M) {
                    float2 o = make_float2(acc[i][j][2] + bx, acc[i][j][3] + by);
                    __stcs((float2*)(C + (size_t)(m + 8) * N + n), o);
                }
            }
        }
    }
}

// ------------------------------ launcher ----------------------------------------
extern "C" void kernel_launch(void* const* d_in, const int* in_sizes, int n_in,
                              void* d_out, int out_size)
{
    const int*   gi_src  = (const int*)d_in[3];
    const int*   gi_dst  = (const int*)d_in[4];
    const int*   gu_src  = (const int*)d_in[5];
    const int*   gu_dst  = (const int*)d_in[6];
    const float* emb_u   = (const float*)d_in[8];
    const float* emb_i   = (const float*)d_in[9];
    const float* Wl1     = (const float*)d_in[10];
    const float* Wr1     = (const float*)d_in[11];
    const float* b1      = (const float*)d_in[12];
    const float* Wl2     = (const float*)d_in[13];
    const float* Wr2     = (const float*)d_in[14];
    const float* b2      = (const float*)d_in[15];
    const float* Wp      = (const float*)d_in[16];
    const float* bp      = (const float*)d_in[17];
    float*       out     = (float*)d_out;

    ZeroRegion* zr;
    int *off_i, *off_u, *nbr_i, *nbr_u;
    __half *embih, *embuh, *wt, *w1c, *w2c, *x1, *x2, *i1h, *u1h, *af, *bf;
    cudaGetSymbolAddress((void**)&zr,     g_zr);
    cudaGetSymbolAddress((void**)&off_i,  g_off_i);
    cudaGetSymbolAddress((void**)&off_u,  g_off_u);
    cudaGetSymbolAddress((void**)&nbr_i,  g_nbr_i);
    cudaGetSymbolAddress((void**)&nbr_u,  g_nbr_u);
    cudaGetSymbolAddress((void**)&embih,  g_embih);
    cudaGetSymbolAddress((void**)&embuh,  g_embuh);
    cudaGetSymbolAddress((void**)&wt,     g_Wt);
    cudaGetSymbolAddress((void**)&w1c,    g_W1c);
    cudaGetSymbolAddress((void**)&w2c,    g_W2c);
    cudaGetSymbolAddress((void**)&x1,     g_X1);
    cudaGetSymbolAddress((void**)&x2,     g_X2);
    cudaGetSymbolAddress((void**)&i1h,    g_i1h);
    cudaGetSymbolAddress((void**)&u1h,    g_u1h);
    cudaGetSymbolAddress((void**)&af,     g_Af);
    cudaGetSymbolAddress((void**)&bf,     g_Bf);

    int* cnt_i = zr->cnt_i;
    int* cnt_u = zr->cnt_u;
    int* pos_i = zr->pos_i;
    int* pos_u = zr->pos_u;

    cudaMemsetAsync(zr, 0, sizeof(ZeroRegion));

    int smemGcat = (64 + 128) * SMSTRIDE * sizeof(__half);
    int smemPipe = 4 * 128 * CSTRIDE * sizeof(__half);   // 73728
    cudaFuncSetAttribute(lin_pair_gemm, cudaFuncAttributeMaxDynamicSharedMemorySize, smemPipe);
    cudaFuncSetAttribute(gemm_f16,      cudaFuncAttributeMaxDynamicSharedMemorySize, smemPipe);
    cudaFuncSetAttribute(gcat_gemm,     cudaFuncAttributeMaxDynamicSharedMemorySize, smemGcat);

    // fused prep: emb->fp16, edge histogram, Wp^T, 7 weight transposes
    prep_kernel<<<PREP_TOTAL, 256>>>((const float4*)emb_i, (const float4*)emb_u,
                                     (uint2*)embih, (uint2*)embuh,
                                     gi_src, gu_src, cnt_i, cnt_u,
                                     Wp, bf, Wr1, Wl1, Wl2, Wr2, wt, w1c, w2c);

    // CSR scan + fill
    scan_kernel<<<2, 1024>>>(cnt_i, off_i, cnt_u, off_u, NGc);
    fill_kernel<<<(HIST_THREADS + 255) / 256, 256>>>(gi_src, gi_dst, gu_src, gu_dst,
                                                     off_i, off_u, pos_i, pos_u, nbr_i, nbr_u);

    // i1 / u1 merged pipelined fp16 tensor GEMM
    int nbI = (NIc + 127) / 128, nbU = (NUc + 127) / 128;
    lin_pair_gemm<<<nbI + nbU, 256, smemPipe>>>(embih, wt, b1 + 0 * D, i1h, NIc,
                                                embuh, wt + D * D, b1 + 2 * D, u1h, NUc);

    // layer-1 aggregate -> X1
    aggregate_kernel<<<(2 * NGc * 32 + 255) / 256, 256>>>(off_i, nbr_i, cnt_i, (const uint2*)embih,
                                                          off_u, nbr_u, cnt_u, (const uint2*)embuh,
                                                          x1, 256);

    // g1 = relu(X1 @ W1c^T + b) -> X2 cols 256..383
    gcat_gemm<<<(NGc + 63) / 64, 256, smemGcat>>>(x1, 256, 256, w1c,
                                                  b1 + 1 * D, b1 + 3 * D, x2 + 256, 384, NGc);

    // layer-2 aggregate -> X2 cols 0..255
    aggregate_kernel<<<(2 * NGc * 32 + 255) / 256, 256>>>(off_i, nbr_i, cnt_i, (const uint2*)i1h,
                                                          off_u, nbr_u, cnt_u, (const uint2*)u1h,
                                                          x2, 384);

    // g2 = relu(X2 @ W2c^T + b) -> af
    gcat_gemm<<<(NGc + 63) / 64, 256, smemGcat>>>(x2, 384, 384, w2c,
                                                  b2 + 1 * D, b2 + 3 * D, af, 128, NGc);

    // out = g2 @ WpT^T + bp  via pipelined fp16 tensor GEMM
    dim3 grid((NIc + 127) / 128, (NGc + 127) / 128);
    gemm_f16<<<grid, 256, smemPipe>>>(af, bf, bp, out, NGc, NIc);
}

// round 16
// speedup vs baseline: 1.4985x; 1.0258x over previous
#include <cuda_runtime.h>
#include <cuda_fp16.h>
#include <cstdint>

#define D    128
#define NGc  10000
#define NUc  100000
#define NIc  20000
#define EGIc 400000
#define EGUc 400000

// ---------------- scratch (device globals; no allocation allowed) -------------
struct ZeroRegion {
    int cnt_i[NGc];
    int cnt_u[NGc];
    int pos_i[NGc];
    int pos_u[NGc];
};
__device__ ZeroRegion g_zr;

__device__ int    g_off_i[NGc];
__device__ int    g_off_u[NGc];
__device__ int    g_nbr_i[EGIc];
__device__ int    g_nbr_u[EGUc];
__device__ __half g_embih[NIc * D];
__device__ __half g_embuh[NUc * D];
__device__ __half g_Wt[2 * D * D];      // Wr1[0]^T, Wr1[2]^T fp16
__device__ __half g_W1c[D * 256];       // [Wl1[1];Wl1[3]]^T
__device__ __half g_W2c[D * 384];       // [Wl2[1];Wl2[3];Wr2[1]+Wr2[3]]^T
__device__ __half g_X1[NGc * 256];      // [aggI, aggU] fp16
__device__ __half g_X2[NGc * 384];      // [agg2I, agg2U, g1] fp16
__device__ __half g_i1h[NIc * D];
__device__ __half g_u1h[NUc * D];
__device__ __half g_Af[NGc * D];        // g2 fp16
__device__ __half g_Bf[NIc * D];        // WpT fp16: [n][k]

// ---------------- helpers -------------------------------------------------------
__device__ __forceinline__ float4 h4_to_f4(uint2 r)
{
    __half2 a = *(__half2*)&r.x;
    __half2 b = *(__half2*)&r.y;
    float2 fa = __half22float2(a), fb = __half22float2(b);
    return make_float4(fa.x, fa.y, fb.x, fb.y);
}
__device__ __forceinline__ uint2 f4_to_h4(float4 v)
{
    __half2 a = __floats2half2_rn(v.x, v.y);
    __half2 b = __floats2half2_rn(v.z, v.w);
    uint2 r;
    r.x = *(uint32_t*)&a;
    r.y = *(uint32_t*)&b;
    return r;
}

// ================= fused prep: emb convert + hist + Wp^T + 7 weight^T ===========
// emb section: 4 float4s per thread (exact: EMB_N4 == 4 * EMB_THREADS)
#define EMB_N4        ((NIc + NUc) * 32)                      // 3,840,000
#define EMB_THREADS   (EMB_N4 / 4)                            // 960,000
#define PREP_EMB_BLK  (EMB_THREADS / 256)                     // 3750
// hist section: 4 grid-strided edges per thread (stride = HIST_THREADS)
#define HIST_THREADS  ((EGIc + EGUc + 3) / 4)                 // 200000
#define PREP_HIST_BLK ((HIST_THREADS + 255) / 256)            // 782
#define PREP_WP_BLK   ((NIc / 32) * (D / 32))                 // 2500
#define PREP_WB_BLK   (4 * 4 * 7)                             // 112
#define PREP_TOTAL    (PREP_EMB_BLK + PREP_HIST_BLK + PREP_WP_BLK + PREP_WB_BLK)

__global__ void prep_kernel(const float4* __restrict__ xi, const float4* __restrict__ xu,
                            uint2* __restrict__ yi, uint2* __restrict__ yu,
                            const int* __restrict__ gi_s, const int* __restrict__ gu_s,
                            int* __restrict__ cnt_i, int* __restrict__ cnt_u,
                            const float* __restrict__ Wp, __half* __restrict__ bf,
                            const float* __restrict__ Wr1, const float* __restrict__ Wl1,
                            const float* __restrict__ Wl2, const float* __restrict__ Wr2,
                            __half* __restrict__ wt, __half* __restrict__ w1c,
                            __half* __restrict__ w2c)
{
    __shared__ float t[32][33];
    int b = blockIdx.x;
    int tid = threadIdx.x;

    if (b < PREP_EMB_BLK) {
        // ---- emb fp32 -> fp16, 4 float4s per thread for MLP ----
        int base = b * 256 + tid;                 // < EMB_THREADS always
        const int NI4 = NIc * 32;
        float4 v[4];
#pragma unroll
        for (int q = 0; q < 4; q++) {
            int i = base + q * EMB_THREADS;
            v[q] = (i < NI4) ? xi[i] : xu[i - NI4];
        }
#pragma unroll
        for (int q = 0; q < 4; q++) {
            int i = base + q * EMB_THREADS;
            if (i < NI4) yi[i] = f4_to_h4(v[q]);
            else         yu[i - NI4] = f4_to_h4(v[q]);
        }
        return;
    }
    b -= PREP_EMB_BLK;
    if (b < PREP_HIST_BLK) {
        int base = b * 256 + tid;
        if (base < HIST_THREADS) {          // guard: stride == HIST_THREADS exactly
#pragma unroll
            for (int q = 0; q < 4; q++) {
                int i = base + q * HIST_THREADS;
                if (i < EGIc) atomicAdd(cnt_i + __ldg(gi_s + i), 1);
                else if (i < EGIc + EGUc) atomicAdd(cnt_u + __ldg(gu_s + i - EGIc), 1);
            }
        }
        return;
    }
    b -= PREP_HIST_BLK;
    int tx = tid & 31, ty = tid >> 5;
    if (b < PREP_WP_BLK) {
        int n0 = (b % (NIc / 32)) * 32;
        int k0 = (b / (NIc / 32)) * 32;
#pragma unroll
        for (int r = ty; r < 32; r += 8)
            t[r][tx] = Wp[(size_t)(k0 + r) * NIc + n0 + tx];
        __syncthreads();
#pragma unroll
        for (int r = ty; r < 32; r += 8)
            bf[(size_t)(n0 + r) * D + k0 + tx] = __float2half_rn(t[tx][r]);
        return;
    }
    b -= PREP_WP_BLK;
    {
        int job = b >> 4;
        int cx = b & 3, cy = (b >> 2) & 3;
        const float* src = nullptr;
        const float* src2 = nullptr;
        __half* dst = nullptr;
        int ldw = 128, koff = 0;
        switch (job) {
            case 0: src = Wr1;               dst = wt;          ldw = 128; koff = 0;   break;
            case 1: src = Wr1 + 2 * D * D;   dst = wt + D * D;  ldw = 128; koff = 0;   break;
            case 2: src = Wl1 + 1 * D * D;   dst = w1c;         ldw = 256; koff = 0;   break;
            case 3: src = Wl1 + 3 * D * D;   dst = w1c;         ldw = 256; koff = 128; break;
            case 4: src = Wl2 + 1 * D * D;   dst = w2c;         ldw = 384; koff = 0;   break;
            case 5: src = Wl2 + 3 * D * D;   dst = w2c;         ldw = 384; koff = 128; break;
            default: src = Wr2 + 1 * D * D;  src2 = Wr2 + 3 * D * D; dst = w2c; ldw = 384; koff = 256; break;
        }
        int c0 = cx * 32, k0 = cy * 32;
#pragma unroll
        for (int r = ty; r < 32; r += 8) {
            float v = src[(k0 + r) * D + c0 + tx];
            if (src2) v += src2[(k0 + r) * D + c0 + tx];
            t[r][tx] = v;
        }
        __syncthreads();
#pragma unroll
        for (int r = ty; r < 32; r += 8)
            dst[(size_t)(c0 + r) * ldw + koff + k0 + tx] = __float2half_rn(t[tx][r]);
    }
}

// ================= CSR scan (warp-shuffle) + fill ===============================
__global__ void __launch_bounds__(1024, 1)
scan_kernel(const int* __restrict__ cnt_i, int* __restrict__ off_i,
            const int* __restrict__ cnt_u, int* __restrict__ off_u, int n)
{
    const int* cnt = blockIdx.x == 0 ? cnt_i : cnt_u;
    int* off = blockIdx.x == 0 ? off_i : off_u;
    __shared__ int warpsum[32];
    __shared__ int carry;
    int tid = threadIdx.x;
    int lane = tid & 31, wid = tid >> 5;
    if (tid == 0) carry = 0;
    __syncthreads();
    for (int base = 0; base < n; base += 1024) {
        int i = base + tid;
        int v = (i < n) ? cnt[i] : 0;
        int x = v;
#pragma unroll
        for (int s = 1; s < 32; s <<= 1) {
            int t = __shfl_up_sync(0xFFFFFFFF, x, s);
            if (lane >= s) x += t;
        }
        if (lane == 31) warpsum[wid] = x;
        __syncthreads();
        if (wid == 0) {
            int y = warpsum[lane];
#pragma unroll
            for (int s = 1; s < 32; s <<= 1) {
                int t = __shfl_up_sync(0xFFFFFFFF, y, s);
                if (lane >= s) y += t;
            }
            warpsum[lane] = y;
        }
        __syncthreads();
        int incl = x + (wid > 0 ? warpsum[wid - 1] : 0);
        if (i < n) off[i] = carry + incl - v;
        __syncthreads();
        if (tid == 0) carry += warpsum[31];
        __syncthreads();
    }
}

// fill: 4 grid-strided edges per thread (stride = HIST_THREADS), guarded
__global__ void fill_kernel(const int* __restrict__ gi_s, const int* __restrict__ gi_d,
                            const int* __restrict__ gu_s, const int* __restrict__ gu_d,
                            const int* __restrict__ off_i, const int* __restrict__ off_u,
                            int* __restrict__ pos_i, int* __restrict__ pos_u,
                            int* __restrict__ nbr_i, int* __restrict__ nbr_u)
{
    int base = blockIdx.x * blockDim.x + threadIdx.x;
    if (base >= HIST_THREADS) return;
#pragma unroll
    for (int q = 0; q < 4; q++) {
        int i = base + q * HIST_THREADS;
        if (i < EGIc) {
            int g = __ldg(gi_s + i);
            int p = atomicAdd(pos_i + g, 1);
            nbr_i[__ldg(off_i + g) + p] = __ldg(gi_d + i);
        } else if (i < EGIc + EGUc) {
            int e = i - EGIc;
            int g = __ldg(gu_s + e);
            int p = atomicAdd(pos_u + g, 1);
            nbr_u[__ldg(off_u + g) + p] = __ldg(gu_d + e);
        }
    }
}

// ===== gather-aggregate: one warp per (group, relation); mean -> fp16 into X ====
__global__ void aggregate_kernel(const int* __restrict__ off_i, const int* __restrict__ nbr_i,
                                 const int* __restrict__ cnt_i, const uint2* __restrict__ fi,
                                 const int* __restrict__ off_u, const int* __restrict__ nbr_u,
                                 const int* __restrict__ cnt_u, const uint2* __restrict__ fu,
                                 __half* __restrict__ X, int ldx)
{
    int gw = (blockIdx.x * blockDim.x + threadIdx.x) >> 5;
    int lane = threadIdx.x & 31;
    if (gw >= 2 * NGc) return;
    bool isU = gw >= NGc;
    int g = isU ? gw - NGc : gw;
    const int* off = isU ? off_u : off_i;
    const int* nbr = isU ? nbr_u : nbr_i;
    const int* cnt = isU ? cnt_u : cnt_i;
    const uint2* f = isU ? fu : fi;

    int base = __ldg(off + g);
    int deg = __ldg(cnt + g);
    float4 acc = make_float4(0.f, 0.f, 0.f, 0.f);
    int j = 0;
    for (; j + 8 <= deg; j += 8) {
        int ii[8];
#pragma unroll
        for (int t = 0; t < 8; t++) ii[t] = __ldg(nbr + base + j + t);
        uint2 rr[8];
#pragma unroll
        for (int t = 0; t < 8; t++) rr[t] = __ldg(f + (size_t)ii[t] * 32 + lane);
#pragma unroll
        for (int t = 0; t < 8; t++) {
            float4 v = h4_to_f4(rr[t]);
            acc.x += v.x; acc.y += v.y; acc.z += v.z; acc.w += v.w;
        }
    }
    for (; j < deg; j++) {
        int i0 = __ldg(nbr + base + j);
        float4 v0 = h4_to_f4(__ldg(f + (size_t)i0 * 32 + lane));
        acc.x += v0.x; acc.y += v0.y; acc.z += v0.z; acc.w += v0.w;
    }
    float inv = 1.f / (float)max(deg, 1);
    acc.x *= inv; acc.y *= inv; acc.z *= inv; acc.w *= inv;
    *(uint2*)(X + (size_t)g * ldx + (isU ? 128 : 0) + lane * 4) = f4_to_h4(acc);
}

// ================= fp16 HMMA building blocks ====================================
__device__ __forceinline__ void mma16816(float* c, const uint32_t* a, const uint32_t* b)
{
    asm volatile(
        "mma.sync.aligned.m16n8k16.row.col.f32.f16.f16.f32 "
        "{%0,%1,%2,%3}, {%4,%5,%6,%7}, {%8,%9}, {%0,%1,%2,%3};\n"
        : "+f"(c[0]), "+f"(c[1]), "+f"(c[2]), "+f"(c[3])
        : "r"(a[0]), "r"(a[1]), "r"(a[2]), "r"(a[3]), "r"(b[0]), "r"(b[1]));
}
__device__ __forceinline__ void ldsm_x4(uint32_t* r, uint32_t addr)
{
    asm volatile("ldmatrix.sync.aligned.m8n8.x4.shared.b16 {%0,%1,%2,%3}, [%4];"
                 : "=r"(r[0]), "=r"(r[1]), "=r"(r[2]), "=r"(r[3]) : "r"(addr));
}
__device__ __forceinline__ void cp16(uint32_t dst, const void* src, bool pred)
{
    asm volatile("cp.async.ca.shared.global [%0], [%1], 16, %2;"
                 :: "r"(dst), "l"(src), "r"(pred ? 16 : 0));
}
#define CP_COMMIT() asm volatile("cp.async.commit_group;" ::: "memory")
#define CP_WAIT(n)  asm volatile("cp.async.wait_group %0;" :: "n"(n) : "memory")

#define SMSTRIDE 136   // halves per smem row (padded) — gcat
#define CSTRIDE  72    // halves per row in pipelined chunk buffers (144B)

// ------ generic: out[M,128] = relu(X[M,K] @ Wt[128,K]^T + ba + bb) in fp16 ------
__global__ void __launch_bounds__(256, 2)
gcat_gemm(const __half* __restrict__ X, int ldx, int K,
          const __half* __restrict__ Wt,
          const float* __restrict__ ba, const float* __restrict__ bb,
          __half* __restrict__ out, int ldo, int M)
{
    extern __shared__ __half sm[];
    __half* As = sm;                       // 64 x SMSTRIDE
    __half* Bs = As + 64 * SMSTRIDE;       // 128 x SMSTRIDE

    int tid = threadIdx.x;
    int m0 = blockIdx.x * 64;
    int lane = tid & 31, w = tid >> 5;
    int r = lane >> 2, c2 = (lane & 3) * 2;

    float acc[4][2][4];
#pragma unroll
    for (int i = 0; i < 4; i++)
#pragma unroll
        for (int j = 0; j < 2; j++)
#pragma unroll
            for (int q = 0; q < 4; q++) acc[i][j][q] = 0.f;

    uint4 zz = make_uint4(0, 0, 0, 0);
    for (int k0 = 0; k0 < K; k0 += 128) {
        __syncthreads();
#pragma unroll
        for (int it = 0; it < 4; it++) {
            int idx = tid + it * 256;
            int row = idx >> 4, c8 = (idx & 15) << 3;
            int gm = m0 + row;
            uint4 v = zz;
            if (gm < M) v = *(const uint4*)(X + (size_t)gm * ldx + k0 + c8);
            *(uint4*)(As + row * SMSTRIDE + c8) = v;
        }
#pragma unroll
        for (int it = 0; it < 8; it++) {
            int idx = tid + it * 256;
            int row = idx >> 4, c8 = (idx & 15) << 3;
            *(uint4*)(Bs + row * SMSTRIDE + c8) = *(const uint4*)(Wt + (size_t)row * K + k0 + c8);
        }
        __syncthreads();

#pragma unroll
        for (int ks = 0; ks < 8; ks++) {
            int kb = ks * 16 + c2;
            uint32_t a[4][4], b[2][2];
#pragma unroll
            for (int i = 0; i < 4; i++) {
                const __half* pa = As + (i * 16 + r) * SMSTRIDE + kb;
                a[i][0] = *(const uint32_t*)(pa);
                a[i][1] = *(const uint32_t*)(pa + 8 * SMSTRIDE);
                a[i][2] = *(const uint32_t*)(pa + 8);
                a[i][3] = *(const uint32_t*)(pa + 8 * SMSTRIDE + 8);
            }
#pragma unroll
            for (int j = 0; j < 2; j++) {
                const __half* pb = Bs + (w * 16 + j * 8 + r) * SMSTRIDE + kb;
                b[j][0] = *(const uint32_t*)(pb);
                b[j][1] = *(const uint32_t*)(pb + 8);
            }
#pragma unroll
            for (int i = 0; i < 4; i++)
#pragma unroll
                for (int j = 0; j < 2; j++)
                    mma16816(acc[i][j], a[i], b[j]);
        }
    }

#pragma unroll
    for (int i = 0; i < 4; i++) {
#pragma unroll
        for (int j = 0; j < 2; j++) {
            int m = m0 + i * 16 + r;
            int n = w * 16 + j * 8 + c2;
            float bx = __ldg(ba + n) + __ldg(bb + n);
            float by = __ldg(ba + n + 1) + __ldg(bb + n + 1);
            if (m < M) {
                __half2 h = __floats2half2_rn(fmaxf(acc[i][j][0] + bx, 0.f),
                                              fmaxf(acc[i][j][1] + by, 0.f));
                *(__half2*)(out + (size_t)m * ldo + n) = h;
            }
            if (m + 8 < M) {
                __half2 h = __floats2half2_rn(fmaxf(acc[i][j][2] + bx, 0.f),
                                              fmaxf(acc[i][j][3] + by, 0.f));
                *(__half2*)(out + (size_t)(m + 8) * ldo + n) = h;
            }
        }
    }
}

// ==== merged i1/u1: pipelined cp.async + ldmatrix; out = relu(X @ Wt^T + b) =====
__global__ void __launch_bounds__(256, 2)
lin_pair_gemm(const __half* __restrict__ Xi, const __half* __restrict__ Wti,
              const float* __restrict__ bi, __half* __restrict__ outi, int Mi,
              const __half* __restrict__ Xu, const __half* __restrict__ Wtu,
              const float* __restrict__ bu, __half* __restrict__ outu, int Mu)
{
    extern __shared__ __half sm[];
    int tid = threadIdx.x;
    int nbI = (Mi + 127) / 128;
    const __half* X;
    const __half* Wt;
    const float* b;
    __half* out;
    int M, m0;
    if ((int)blockIdx.x < nbI) {
        X = Xi; Wt = Wti; b = bi; out = outi; M = Mi; m0 = blockIdx.x * 128;
    } else {
        X = Xu; Wt = Wtu; b = bu; out = outu; M = Mu; m0 = (blockIdx.x - nbI) * 128;
    }

    uint32_t smb = (uint32_t)__cvta_generic_to_shared(sm);
    const uint32_t BUF = 128 * CSTRIDE * 2;

#pragma unroll
    for (int kc = 0; kc < 2; kc++) {
        uint32_t aB = smb + kc * BUF;
        uint32_t bB = smb + (2 + kc) * BUF;
#pragma unroll
        for (int it = 0; it < 4; it++) {
            int idx = tid + it * 256;
            int row = idx >> 3, c16 = idx & 7;
            int gm = m0 + row;
            bool ok = gm < M;
            const __half* src = X + (size_t)(ok ? gm : 0) * 128 + kc * 64 + c16 * 8;
            cp16(aB + row * (CSTRIDE * 2) + c16 * 16, src, ok);
        }
#pragma unroll
        for (int it = 0; it < 4; it++) {
            int idx = tid + it * 256;
            int row = idx >> 3, c16 = idx & 7;
            const __half* src = Wt + (size_t)row * 128 + kc * 64 + c16 * 8;
            cp16(bB + row * (CSTRIDE * 2) + c16 * 16, src, true);
        }
        CP_COMMIT();
    }

    int lane = tid & 31, w = tid >> 5;
    int wm = w >> 2, wn = w & 3;
    int r = lane >> 2, c2 = (lane & 3) * 2;
    int aRow = lane & 15, aKh = lane >> 4;
    int bRow = ((lane >> 4) & 1) * 8 + (lane & 7);
    int bKh = (lane >> 3) & 1;

    float acc[4][4][4];
#pragma unroll
    for (int i = 0; i < 4; i++)
#pragma unroll
        for (int j = 0; j < 4; j++)
#pragma unroll
            for (int q = 0; q < 4; q++) acc[i][j][q] = 0.f;

#pragma unroll
    for (int kc = 0; kc < 2; kc++) {
        if (kc == 0) CP_WAIT(1);
        else         CP_WAIT(0);
        __syncthreads();

        uint32_t aB = smb + kc * BUF;
        uint32_t bB = smb + (2 + kc) * BUF;
#pragma unroll
        for (int ks = 0; ks < 4; ks++) {
            uint32_t a[4][4], bb[4][2];
#pragma unroll
            for (int i = 0; i < 4; i++) {
                uint32_t addr = aB + ((wm * 64 + i * 16 + aRow) * CSTRIDE + ks * 16 + aKh * 8) * 2;
                ldsm_x4(a[i], addr);
            }
#pragma unroll
            for (int jp = 0; jp < 2; jp++) {
                uint32_t addr = bB + ((wn * 32 + jp * 16 + bRow) * CSTRIDE + ks * 16 + bKh * 8) * 2;
                uint32_t rr[4];
                ldsm_x4(rr, addr);
                bb[jp * 2][0] = rr[0]; bb[jp * 2][1] = rr[1];
                bb[jp * 2 + 1][0] = rr[2]; bb[jp * 2 + 1][1] = rr[3];
            }
#pragma unroll
            for (int i = 0; i < 4; i++)
#pragma unroll
                for (int j = 0; j < 4; j++)
                    mma16816(acc[i][j], a[i], bb[j]);
        }
        if (kc == 0) __syncthreads();
    }

#pragma unroll
    for (int i = 0; i < 4; i++) {
#pragma unroll
        for (int j = 0; j < 4; j++) {
            int m = m0 + wm * 64 + i * 16 + r;
            int n = wn * 32 + j * 8 + c2;
            float bx = __ldg(b + n), by = __ldg(b + n + 1);
            if (m < M) {
                __half2 h = __floats2half2_rn(fmaxf(acc[i][j][0] + bx, 0.f),
                                              fmaxf(acc[i][j][1] + by, 0.f));
                __stcs((__half2*)(out + (size_t)m * 128 + n), h);
            }
            if (m + 8 < M) {
                __half2 h = __floats2half2_rn(fmaxf(acc[i][j][2] + bx, 0.f),
                                              fmaxf(acc[i][j][3] + by, 0.f));
                __stcs((__half2*)(out + (size_t)(m + 8) * 128 + n), h);
            }
        }
    }
}

// ====== final GEMM: cp.async double-buffered K-split + ldmatrix fragments =======
__global__ void __launch_bounds__(256, 2)
gemm_f16(const __half* __restrict__ A, const __half* __restrict__ B,
         const float* __restrict__ bias, float* __restrict__ C, int M, int N)
{
    extern __shared__ __half sm[];
    int tid = threadIdx.x;
    int m0 = blockIdx.y * 128, n0 = blockIdx.x * 128;
    uint32_t smb = (uint32_t)__cvta_generic_to_shared(sm);
    const uint32_t BUF = 128 * CSTRIDE * 2;

#pragma unroll
    for (int kc = 0; kc < 2; kc++) {
        uint32_t aB = smb + kc * BUF;
        uint32_t bB = smb + (2 + kc) * BUF;
#pragma unroll
        for (int it = 0; it < 4; it++) {
            int idx = tid + it * 256;
            int row = idx >> 3, c16 = idx & 7;
            int gm = m0 + row;
            bool ok = gm < M;
            const __half* src = A + (size_t)(ok ? gm : 0) * 128 + kc * 64 + c16 * 8;
            cp16(aB + row * (CSTRIDE * 2) + c16 * 16, src, ok);
        }
#pragma unroll
        for (int it = 0; it < 4; it++) {
            int idx = tid + it * 256;
            int row = idx >> 3, c16 = idx & 7;
            int gn = n0 + row;
            bool ok = gn < N;
            const __half* src = B + (size_t)(ok ? gn : 0) * 128 + kc * 64 + c16 * 8;
            cp16(bB + row * (CSTRIDE * 2) + c16 * 16, src, ok);
        }
        CP_COMMIT();
    }

    int lane = tid & 31, w = tid >> 5;
    int wm = w >> 2, wn = w & 3;
    int r = lane >> 2, c2 = (lane & 3) * 2;
    int aRow = lane & 15, aKh = lane >> 4;
    int bRow = ((lane >> 4) & 1) * 8 + (lane & 7);
    int bKh = (lane >> 3) & 1;

    float acc[4][4][4];
#pragma unroll
    for (int i = 0; i < 4; i++)
#pragma unroll
        for (int j = 0; j < 4; j++)
#pragma unroll
            for (int q = 0; q < 4; q++) acc[i][j][q] = 0.f;

#pragma unroll
    for (int kc = 0; kc < 2; kc++) {
        if (kc == 0) CP_WAIT(1);
        else         CP_WAIT(0);
        __syncthreads();

        uint32_t aB = smb + kc * BUF;
        uint32_t bB = smb + (2 + kc) * BUF;
#pragma unroll
        for (int ks = 0; ks < 4; ks++) {
            uint32_t a[4][4], b[4][2];
#pragma unroll
            for (int i = 0; i < 4; i++) {
                uint32_t addr = aB + ((wm * 64 + i * 16 + aRow) * CSTRIDE + ks * 16 + aKh * 8) * 2;
                ldsm_x4(a[i], addr);
            }
#pragma unroll
            for (int jp = 0; jp < 2; jp++) {
                uint32_t addr = bB + ((wn * 32 + jp * 16 + bRow) * CSTRIDE + ks * 16 + bKh * 8) * 2;
                uint32_t rr[4];
                ldsm_x4(rr, addr);
                b[jp * 2][0] = rr[0]; b[jp * 2][1] = rr[1];
                b[jp * 2 + 1][0] = rr[2]; b[jp * 2 + 1][1] = rr[3];
            }
#pragma unroll
            for (int i = 0; i < 4; i++)
#pragma unroll
                for (int j = 0; j < 4; j++)
                    mma16816(acc[i][j], a[i], b[j]);
        }
        if (kc == 0) __syncthreads();
    }

#pragma unroll
    for (int i = 0; i < 4; i++) {
#pragma unroll
        for (int j = 0; j < 4; j++) {
            int m = m0 + wm * 64 + i * 16 + r;
            int n = n0 + wn * 32 + j * 8 + c2;
            if (n < N) {
                float bx = __ldg(bias + n), by = __ldg(bias + n + 1);
                if (m < M) {
                    float2 o = make_float2(acc[i][j][0] + bx, acc[i][j][1] + by);
                    __stcs((float2*)(C + (size_t)m * N + n), o);
                }
                if (m + 8 < M) {
                    float2 o = make_float2(acc[i][j][2] + bx, acc[i][j][3] + by);
                    __stcs((float2*)(C + (size_t)(m + 8) * N + n), o);
                }
            }
        }
    }
}

// ------------------------------ launcher ----------------------------------------
extern "C" void kernel_launch(void* const* d_in, const int* in_sizes, int n_in,
                              void* d_out, int out_size)
{
    const int*   gi_src  = (const int*)d_in[3];
    const int*   gi_dst  = (const int*)d_in[4];
    const int*   gu_src  = (const int*)d_in[5];
    const int*   gu_dst  = (const int*)d_in[6];
    const float* emb_u   = (const float*)d_in[8];
    const float* emb_i   = (const float*)d_in[9];
    const float* Wl1     = (const float*)d_in[10];
    const float* Wr1     = (const float*)d_in[11];
    const float* b1      = (const float*)d_in[12];
    const float* Wl2     = (const float*)d_in[13];
    const float* Wr2     = (const float*)d_in[14];
    const float* b2      = (const float*)d_in[15];
    const float* Wp      = (const float*)d_in[16];
    const float* bp      = (const float*)d_in[17];
    float*       out     = (float*)d_out;

    ZeroRegion* zr;
    int *off_i, *off_u, *nbr_i, *nbr_u;
    __half *embih, *embuh, *wt, *w1c, *w2c, *x1, *x2, *i1h, *u1h, *af, *bf;
    cudaGetSymbolAddress((void**)&zr,     g_zr);
    cudaGetSymbolAddress((void**)&off_i,  g_off_i);
    cudaGetSymbolAddress((void**)&off_u,  g_off_u);
    cudaGetSymbolAddress((void**)&nbr_i,  g_nbr_i);
    cudaGetSymbolAddress((void**)&nbr_u,  g_nbr_u);
    cudaGetSymbolAddress((void**)&embih,  g_embih);
    cudaGetSymbolAddress((void**)&embuh,  g_embuh);
    cudaGetSymbolAddress((void**)&wt,     g_Wt);
    cudaGetSymbolAddress((void**)&w1c,    g_W1c);
    cudaGetSymbolAddress((void**)&w2c,    g_W2c);
    cudaGetSymbolAddress((void**)&x1,     g_X1);
    cudaGetSymbolAddress((void**)&x2,     g_X2);
    cudaGetSymbolAddress((void**)&i1h,    g_i1h);
    cudaGetSymbolAddress((void**)&u1h,    g_u1h);
    cudaGetSymbolAddress((void**)&af,     g_Af);
    cudaGetSymbolAddress((void**)&bf,     g_Bf);

    int* cnt_i = zr->cnt_i;
    int* cnt_u = zr->cnt_u;
    int* pos_i = zr->pos_i;
    int* pos_u = zr->pos_u;

    cudaMemsetAsync(zr, 0, sizeof(ZeroRegion));

    int smemGcat = (64 + 128) * SMSTRIDE * sizeof(__half);
    int smemPipe = 4 * 128 * CSTRIDE * sizeof(__half);   // 73728
    cudaFuncSetAttribute(lin_pair_gemm, cudaFuncAttributeMaxDynamicSharedMemorySize, smemPipe);
    cudaFuncSetAttribute(gemm_f16,      cudaFuncAttributeMaxDynamicSharedMemorySize, smemPipe);
    cudaFuncSetAttribute(gcat_gemm,     cudaFuncAttributeMaxDynamicSharedMemorySize, smemGcat);

    // fused prep: emb->fp16, edge histogram, Wp^T, 7 weight transposes
    prep_kernel<<<PREP_TOTAL, 256>>>((const float4*)emb_i, (const float4*)emb_u,
                                     (uint2*)embih, (uint2*)embuh,
                                     gi_src, gu_src, cnt_i, cnt_u,
                                     Wp, bf, Wr1, Wl1, Wl2, Wr2, wt, w1c, w2c);

    // CSR scan + fill
    scan_kernel<<<2, 1024>>>(cnt_i, off_i, cnt_u, off_u, NGc);
    fill_kernel<<<(HIST_THREADS + 255) / 256, 256>>>(gi_src, gi_dst, gu_src, gu_dst,
                                                     off_i, off_u, pos_i, pos_u, nbr_i, nbr_u);

    // i1 / u1 merged pipelined fp16 tensor GEMM
    int nbI = (NIc + 127) / 128, nbU = (NUc + 127) / 128;
    lin_pair_gemm<<<nbI + nbU, 256, smemPipe>>>(embih, wt, b1 + 0 * D, i1h, NIc,
                                                embuh, wt + D * D, b1 + 2 * D, u1h, NUc);

    // layer-1 aggregate -> X1
    aggregate_kernel<<<(2 * NGc * 32 + 255) / 256, 256>>>(off_i, nbr_i, cnt_i, (const uint2*)embih,
                                                          off_u, nbr_u, cnt_u, (const uint2*)embuh,
                                                          x1, 256);

    // g1 = relu(X1 @ W1c^T + b) -> X2 cols 256..383
    gcat_gemm<<<(NGc + 63) / 64, 256, smemGcat>>>(x1, 256, 256, w1c,
                                                  b1 + 1 * D, b1 + 3 * D, x2 + 256, 384, NGc);

    // layer-2 aggregate -> X2 cols 0..255
    aggregate_kernel<<<(2 * NGc * 32 + 255) / 256, 256>>>(off_i, nbr_i, cnt_i, (const uint2*)i1h,
                                                          off_u, nbr_u, cnt_u, (const uint2*)u1h,
                                                          x2, 384);

    // g2 = relu(X2 @ W2c^T + b) -> af
    gcat_gemm<<<(NGc + 63) / 64, 256, smemGcat>>>(x2, 384, 384, w2c,
                                                  b2 + 1 * D, b2 + 3 * D, af, 128, NGc);

    // out = g2 @ WpT^T + bp  via pipelined fp16 tensor GEMM
    dim3 grid((NIc + 127) / 128, (NGc + 127) / 128);
    gemm_f16<<<grid, 256, smemPipe>>>(af, bf, bp, out, NGc, NIc);
}